// round 5
// baseline (speedup 1.0000x reference)
#include <cuda_runtime.h>
#include <cstdint>

// Quantized SiLU (per-row scales), S=8192 rows, H=4096 cols.
//   x_f   = x * scale_x[row]
//   y_q   = clip(rint(sigmoid(x_f) / scale_y[row]), -127, 127)   (sigmoid>0 -> only upper clip)
//   y_f   = y_q * scale_y[row]
//   out_q = clip(rint((x_f * y_f) / scale_out[row]), -127, 127)
//
// Fusion: out_f / scale_out = f * y_q * (scale_x*scale_y/scale_out), so xf is
// never materialized; sigmoid argument is f * (-scale_x*log2e) fed to EX2.
//
// x arrives promoted to a 4-byte type (int32 or float32); values always in
// [-127,127], so dtype decodes per element branch-free (wrong interpretation
// is always out of range). Output: float32 [S*H out_q][S scale_out].

__device__ __forceinline__ float ex2_approx(float x) {
    float r;
    asm("ex2.approx.f32 %0, %1;" : "=f"(r) : "f"(x));
    return r;
}
__device__ __forceinline__ float rcp_approx(float x) {
    float r;
    asm("rcp.approx.f32 %0, %1;" : "=f"(r) : "f"(x));
    return r;
}

__device__ __forceinline__ float decode_elem(int w) {
    float fi = (float)w;            // int32 interpretation
    float ff = __int_as_float(w);   // float32 interpretation
    return (fabsf(fi) > 127.5f) ? ff : fi;   // real values are in [-127,127]
}

// c_ex2 = -scale_x*log2(e); c_xyo = scale_x*scale_y/scale_out
__device__ __forceinline__ float silu_q(float f, float c_ex2,
                                        float inv_sy, float c_xyo) {
    float e   = ex2_approx(f * c_ex2);            // exp(-x_f)
    float sig = rcp_approx(1.0f + e);             // sigmoid(x_f)
    float yq  = fminf(rintf(sig * inv_sy), 127.0f);
    float oq  = rintf(f * yq * c_xyo);
    return fminf(fmaxf(oq, -127.0f), 127.0f);
}

// Fast path: H == 4096. One CTA per row, 256 threads, 4 front-batched int4
// loads (MLP=4), 4 float4 stores. Thread 0 writes the row's scale_out tail.
__global__ void __launch_bounds__(256) silu_quant_main_kernel(
    const int4* __restrict__ x,
    const float* __restrict__ scale_x_v,
    const float* __restrict__ scale_y_v,
    const float* __restrict__ scale_out_v,
    float4* __restrict__ out,
    float* __restrict__ tail_dst,
    int write_tail)
{
    int row = blockIdx.x;
    float scale_x = __ldg(&scale_x_v[row]);
    float scale_y = __ldg(&scale_y_v[row]);
    float scale_o = __ldg(&scale_out_v[row]);
    float inv_sy  = 1.0f / scale_y;
    float c_ex2   = -scale_x * 1.44269504088896340736f;
    float c_xyo   = scale_x * scale_y * (1.0f / scale_o);

    long base = (long)row * 1024 + threadIdx.x;
    int4 v0 = x[base];
    int4 v1 = x[base + 256];
    int4 v2 = x[base + 512];
    int4 v3 = x[base + 768];

    float4 r0, r1, r2, r3;
    r0.x = silu_q(decode_elem(v0.x), c_ex2, inv_sy, c_xyo);
    r0.y = silu_q(decode_elem(v0.y), c_ex2, inv_sy, c_xyo);
    r0.z = silu_q(decode_elem(v0.z), c_ex2, inv_sy, c_xyo);
    r0.w = silu_q(decode_elem(v0.w), c_ex2, inv_sy, c_xyo);
    r1.x = silu_q(decode_elem(v1.x), c_ex2, inv_sy, c_xyo);
    r1.y = silu_q(decode_elem(v1.y), c_ex2, inv_sy, c_xyo);
    r1.z = silu_q(decode_elem(v1.z), c_ex2, inv_sy, c_xyo);
    r1.w = silu_q(decode_elem(v1.w), c_ex2, inv_sy, c_xyo);
    r2.x = silu_q(decode_elem(v2.x), c_ex2, inv_sy, c_xyo);
    r2.y = silu_q(decode_elem(v2.y), c_ex2, inv_sy, c_xyo);
    r2.z = silu_q(decode_elem(v2.z), c_ex2, inv_sy, c_xyo);
    r2.w = silu_q(decode_elem(v2.w), c_ex2, inv_sy, c_xyo);
    r3.x = silu_q(decode_elem(v3.x), c_ex2, inv_sy, c_xyo);
    r3.y = silu_q(decode_elem(v3.y), c_ex2, inv_sy, c_xyo);
    r3.z = silu_q(decode_elem(v3.z), c_ex2, inv_sy, c_xyo);
    r3.w = silu_q(decode_elem(v3.w), c_ex2, inv_sy, c_xyo);

    out[base]       = r0;
    out[base + 256] = r1;
    out[base + 512] = r2;
    out[base + 768] = r3;

    if (write_tail && threadIdx.x == 0) tail_dst[row] = scale_o;
}

// Generic fallback for unexpected shapes.
__global__ void __launch_bounds__(256) silu_quant_generic_kernel(
    const int* __restrict__ x,
    const float* __restrict__ scale_x_v,
    const float* __restrict__ scale_y_v,
    const float* __restrict__ scale_out_v,
    float* __restrict__ out,
    int H, long total)
{
    long i = (long)blockIdx.x * blockDim.x + threadIdx.x;
    if (i >= total) return;
    int row = (int)(i / H);
    float scale_x = scale_x_v[row];
    float scale_y = scale_y_v[row];
    float inv_sy  = 1.0f / scale_y;
    float c_ex2   = -scale_x * 1.44269504088896340736f;
    float c_xyo   = scale_x * scale_y * (1.0f / scale_out_v[row]);
    out[i] = silu_q(decode_elem(x[i]), c_ex2, inv_sy, c_xyo);
}

__global__ void tail_pad_kernel(const float* __restrict__ scale_o,
                                float* __restrict__ dst, int S, long extra) {
    long i = (long)blockIdx.x * blockDim.x + threadIdx.x;
    if (i >= extra) return;
    dst[i] = (i < S) ? scale_o[i] : 0.0f;
}

extern "C" void kernel_launch(void* const* d_in, const int* in_sizes, int n_in,
                              void* d_out, int out_size) {
    const void* x         = d_in[0];
    const float* scale_x  = (const float*)d_in[1];
    const float* scale_y  = (const float*)d_in[2];
    const float* scale_o  = (const float*)d_in[3];

    int S = in_sizes[1];            // rows (scale_x element count)
    int H = in_sizes[0] / S;        // cols
    long total = (long)S * H;
    long extra = (long)out_size - total;
    float* out = (float*)d_out;

    if (H == 4096) {
        int write_tail = (extra >= (long)S) ? 1 : 0;
        silu_quant_main_kernel<<<S, 256>>>(
            (const int4*)x, scale_x, scale_y, scale_o,
            (float4*)out, out + total, write_tail);
        if (extra > (long)S) {
            long pad = extra - S;
            tail_pad_kernel<<<(int)((pad + 255) / 256), 256>>>(
                scale_o + S, out + total + S, 0, pad);
        } else if (extra > 0 && !write_tail) {
            tail_pad_kernel<<<(int)((extra + 255) / 256), 256>>>(
                scale_o, out + total, (int)extra, extra);
        }
    } else {
        long blocks = (total + 255) / 256;
        silu_quant_generic_kernel<<<(unsigned)blocks, 256>>>(
            (const int*)x, scale_x, scale_y, scale_o, out, H, total);
        if (extra > 0) {
            tail_pad_kernel<<<(int)((extra + 255) / 256), 256>>>(
                scale_o, out + total, (int)(extra < S ? extra : S), extra);
        }
    }
}

// round 6
// speedup vs baseline: 1.0766x; 1.0766x over previous
#include <cuda_runtime.h>
#include <cstdint>

// Quantized SiLU (per-row scales), S=8192 rows, H=4096 cols.
//   x_f   = x * scale_x[row]
//   y_q   = clip(rint(sigmoid(x_f) / scale_y[row]), -127, 127)  (sigmoid>0 -> upper clip only)
//   y_f   = y_q * scale_y[row]
//   out_q = clip(rint((x_f * y_f) / scale_out[row]), -127, 127)
//
// x arrives promoted to a 4-byte type (int32 or float32); values always in
// [-127,127], so dtype decodes per element branch-free.
// Output: float32 [S*H out_q values][S scale_out values].
//
// R6 structure: persistent CTAs (1024 CTAs x 8 contiguous rows), software
// pipeline (row r+1 loads issued before row r compute), streaming cache
// hints (__ldcs/__stcs) on the 256MB stream. Math is the R4-measured-fastest
// sequence (exp2f + __frcp_rn), unchanged.

#define ROWS_PER_CTA 8

__device__ __forceinline__ float decode_elem(int w) {
    float fi = (float)w;            // int32 interpretation
    float ff = __int_as_float(w);   // float32 interpretation
    return (fabsf(fi) > 127.5f) ? ff : fi;   // real values in [-127,127]
}

__device__ __forceinline__ float silu_q(float f, float scale_x, float c_ex2,
                                        float scale_y, float inv_sy, float inv_so) {
    float xf  = f * scale_x;
    float e   = exp2f(f * c_ex2);                 // exp(-x_f)
    float sig = __frcp_rn(1.0f + e);              // sigmoid(x_f)
    float yq  = fminf(rintf(sig * inv_sy), 127.0f);
    float yf  = yq * scale_y;
    float oq  = rintf(xf * yf * inv_so);
    return fminf(fmaxf(oq, -127.0f), 127.0f);
}

__global__ void __launch_bounds__(256, 4) silu_quant_main_kernel(
    const int4* __restrict__ x,
    const float* __restrict__ scale_x_v,
    const float* __restrict__ scale_y_v,
    const float* __restrict__ scale_out_v,
    float4* __restrict__ out,
    float* __restrict__ tail_dst,
    int write_tail, int nrows)
{
    int row0 = blockIdx.x * ROWS_PER_CTA;
    int t = threadIdx.x;

    // ---- prologue: prefetch row0 ----
    long base = (long)row0 * 1024 + t;
    int4 n0 = __ldcs(x + base);
    int4 n1 = __ldcs(x + base + 256);
    int4 n2 = __ldcs(x + base + 512);
    int4 n3 = __ldcs(x + base + 768);
    float nsx = __ldg(&scale_x_v[row0]);
    float nsy = __ldg(&scale_y_v[row0]);
    float nso = __ldg(&scale_out_v[row0]);

    #pragma unroll
    for (int r = 0; r < ROWS_PER_CTA; r++) {
        int row = row0 + r;
        if (row >= nrows) break;

        // shift pipeline: current <- prefetched
        int4 v0 = n0, v1 = n1, v2 = n2, v3 = n3;
        float scale_x = nsx, scale_y = nsy, scale_o = nso;
        long cbase = (long)row * 1024 + t;

        // issue next row's loads before computing current row
        if (r + 1 < ROWS_PER_CTA && row + 1 < nrows) {
            long nb = cbase + 1024;
            n0 = __ldcs(x + nb);
            n1 = __ldcs(x + nb + 256);
            n2 = __ldcs(x + nb + 512);
            n3 = __ldcs(x + nb + 768);
            nsx = __ldg(&scale_x_v[row + 1]);
            nsy = __ldg(&scale_y_v[row + 1]);
            nso = __ldg(&scale_out_v[row + 1]);
        }

        float inv_sy = 1.0f / scale_y;
        float inv_so = 1.0f / scale_o;
        float c_ex2  = -scale_x * 1.44269504088896340736f;

        float4 r0, r1, r2, r3;
        r0.x = silu_q(decode_elem(v0.x), scale_x, c_ex2, scale_y, inv_sy, inv_so);
        r0.y = silu_q(decode_elem(v0.y), scale_x, c_ex2, scale_y, inv_sy, inv_so);
        r0.z = silu_q(decode_elem(v0.z), scale_x, c_ex2, scale_y, inv_sy, inv_so);
        r0.w = silu_q(decode_elem(v0.w), scale_x, c_ex2, scale_y, inv_sy, inv_so);
        r1.x = silu_q(decode_elem(v1.x), scale_x, c_ex2, scale_y, inv_sy, inv_so);
        r1.y = silu_q(decode_elem(v1.y), scale_x, c_ex2, scale_y, inv_sy, inv_so);
        r1.z = silu_q(decode_elem(v1.z), scale_x, c_ex2, scale_y, inv_sy, inv_so);
        r1.w = silu_q(decode_elem(v1.w), scale_x, c_ex2, scale_y, inv_sy, inv_so);
        r2.x = silu_q(decode_elem(v2.x), scale_x, c_ex2, scale_y, inv_sy, inv_so);
        r2.y = silu_q(decode_elem(v2.y), scale_x, c_ex2, scale_y, inv_sy, inv_so);
        r2.z = silu_q(decode_elem(v2.z), scale_x, c_ex2, scale_y, inv_sy, inv_so);
        r2.w = silu_q(decode_elem(v2.w), scale_x, c_ex2, scale_y, inv_sy, inv_so);
        r3.x = silu_q(decode_elem(v3.x), scale_x, c_ex2, scale_y, inv_sy, inv_so);
        r3.y = silu_q(decode_elem(v3.y), scale_x, c_ex2, scale_y, inv_sy, inv_so);
        r3.z = silu_q(decode_elem(v3.z), scale_x, c_ex2, scale_y, inv_sy, inv_so);
        r3.w = silu_q(decode_elem(v3.w), scale_x, c_ex2, scale_y, inv_sy, inv_so);

        __stcs(out + cbase,       r0);
        __stcs(out + cbase + 256, r1);
        __stcs(out + cbase + 512, r2);
        __stcs(out + cbase + 768, r3);

        if (write_tail && t == 0) tail_dst[row] = scale_o;
    }
}

// Generic fallback for unexpected shapes.
__global__ void __launch_bounds__(256) silu_quant_generic_kernel(
    const int* __restrict__ x,
    const float* __restrict__ scale_x_v,
    const float* __restrict__ scale_y_v,
    const float* __restrict__ scale_out_v,
    float* __restrict__ out,
    int H, long total)
{
    long i = (long)blockIdx.x * blockDim.x + threadIdx.x;
    if (i >= total) return;
    int row = (int)(i / H);
    float scale_x = scale_x_v[row];
    float scale_y = scale_y_v[row];
    float inv_sy  = 1.0f / scale_y;
    float inv_so  = 1.0f / scale_out_v[row];
    float c_ex2   = -scale_x * 1.44269504088896340736f;
    out[i] = silu_q(decode_elem(x[i]), scale_x, c_ex2, scale_y, inv_sy, inv_so);
}

__global__ void tail_pad_kernel(const float* __restrict__ scale_o,
                                float* __restrict__ dst, int S, long extra) {
    long i = (long)blockIdx.x * blockDim.x + threadIdx.x;
    if (i >= extra) return;
    dst[i] = (i < S) ? scale_o[i] : 0.0f;
}

extern "C" void kernel_launch(void* const* d_in, const int* in_sizes, int n_in,
                              void* d_out, int out_size) {
    const void* x         = d_in[0];
    const float* scale_x  = (const float*)d_in[1];
    const float* scale_y  = (const float*)d_in[2];
    const float* scale_o  = (const float*)d_in[3];

    int S = in_sizes[1];            // rows (scale_x element count)
    int H = in_sizes[0] / S;        // cols
    long total = (long)S * H;
    long extra = (long)out_size - total;
    float* out = (float*)d_out;

    if (H == 4096) {
        int write_tail = (extra >= (long)S) ? 1 : 0;
        int grid = (S + ROWS_PER_CTA - 1) / ROWS_PER_CTA;   // 1024 for S=8192
        silu_quant_main_kernel<<<grid, 256>>>(
            (const int4*)x, scale_x, scale_y, scale_o,
            (float4*)out, out + total, write_tail, S);
        if (extra > (long)S) {
            long pad = extra - S;
            tail_pad_kernel<<<(int)((pad + 255) / 256), 256>>>(
                scale_o + S, out + total + S, 0, pad);
        } else if (extra > 0 && !write_tail) {
            tail_pad_kernel<<<(int)((extra + 255) / 256), 256>>>(
                scale_o, out + total, (int)extra, extra);
        }
    } else {
        long blocks = (total + 255) / 256;
        silu_quant_generic_kernel<<<(unsigned)blocks, 256>>>(
            (const int*)x, scale_x, scale_y, scale_o, out, H, total);
        if (extra > 0) {
            tail_pad_kernel<<<(int)((extra + 255) / 256), 256>>>(
                scale_o, out + total, (int)(extra < S ? extra : S), extra);
        }
    }
}

// round 7
// speedup vs baseline: 1.1779x; 1.0941x over previous
#include <cuda_runtime.h>
#include <cstdint>

// Quantized SiLU (per-row scales), S=8192 rows, H=4096 cols.
//   x_f   = x * scale_x[row]
//   y_q   = clip(rint(sigmoid(x_f) / scale_y[row]), -127, 127)
//   y_f   = y_q * scale_y[row]
//   out_q = clip(rint((x_f * y_f) / scale_out[row]), -127, 127)
//
// Key structure: x is int8-valued => only 255 distinct inputs per row. Each
// CTA (one row) builds a 255-entry LUT of out_q in shared memory (255 threads,
// one exact silu_q eval each), then the 4096 row elements are index+LDS only
// (~7 inst/elem vs ~18 for direct evaluation). Loads are front-batched before
// the LUT build so HBM latency overlaps it.
//
// x arrives promoted to a 4-byte type (int32 or float32); values always in
// [-127,127], so the index decodes per element branch-free (the wrong
// interpretation is always out of range).
// Output: float32 [S*H out_q values][S scale_out values].

#define LOG2E 1.44269504088896340736f

// word -> LUT index in [0,254]
__device__ __forceinline__ int decode_idx(int w) {
    float fi = (float)w;                              // int32 interpretation
    int   wf = __float2int_rn(__int_as_float(w));     // float32 interpretation
    return ((fabsf(fi) > 127.5f) ? wf : w) + 127;
}

__global__ void __launch_bounds__(256) silu_lut_kernel(
    const int4* __restrict__ x,
    const float* __restrict__ scale_x_v,
    const float* __restrict__ scale_y_v,
    const float* __restrict__ scale_out_v,
    float4* __restrict__ out,
    float* __restrict__ tail_dst,
    int write_tail)
{
    __shared__ float lut[255];
    int row = blockIdx.x;
    int t = threadIdx.x;

    // front-batch the row's loads (MLP=4) so they fly during LUT build
    long base = (long)row * 1024 + t;
    int4 v0 = x[base];
    int4 v1 = x[base + 256];
    int4 v2 = x[base + 512];
    int4 v3 = x[base + 768];

    float scale_x = __ldg(&scale_x_v[row]);
    float scale_y = __ldg(&scale_y_v[row]);
    float scale_o = __ldg(&scale_out_v[row]);

    // build LUT: entry i corresponds to xb = i - 127 (full-precision math)
    if (t < 255) {
        float f   = (float)(t - 127);
        float xf  = f * scale_x;
        float e   = exp2f(-xf * LOG2E);               // exp(-x_f)
        float sig = __frcp_rn(1.0f + e);              // sigmoid(x_f)
        float yq  = fminf(rintf(sig / scale_y), 127.0f);  // sigmoid>0: upper clip only
        float oq  = rintf(xf * (yq * scale_y) / scale_o);
        lut[t] = fminf(fmaxf(oq, -127.0f), 127.0f);
    }
    if (write_tail && t == 0) tail_dst[row] = scale_o;
    __syncthreads();

    float4 r0, r1, r2, r3;
    r0.x = lut[decode_idx(v0.x)];
    r0.y = lut[decode_idx(v0.y)];
    r0.z = lut[decode_idx(v0.z)];
    r0.w = lut[decode_idx(v0.w)];
    r1.x = lut[decode_idx(v1.x)];
    r1.y = lut[decode_idx(v1.y)];
    r1.z = lut[decode_idx(v1.z)];
    r1.w = lut[decode_idx(v1.w)];
    r2.x = lut[decode_idx(v2.x)];
    r2.y = lut[decode_idx(v2.y)];
    r2.z = lut[decode_idx(v2.z)];
    r2.w = lut[decode_idx(v2.w)];
    r3.x = lut[decode_idx(v3.x)];
    r3.y = lut[decode_idx(v3.y)];
    r3.z = lut[decode_idx(v3.z)];
    r3.w = lut[decode_idx(v3.w)];

    out[base]       = r0;
    out[base + 256] = r1;
    out[base + 512] = r2;
    out[base + 768] = r3;
}

// Generic fallback for unexpected shapes (direct evaluation).
__device__ __forceinline__ float decode_elem(int w) {
    float fi = (float)w;
    float ff = __int_as_float(w);
    return (fabsf(fi) > 127.5f) ? ff : fi;
}

__global__ void __launch_bounds__(256) silu_quant_generic_kernel(
    const int* __restrict__ x,
    const float* __restrict__ scale_x_v,
    const float* __restrict__ scale_y_v,
    const float* __restrict__ scale_out_v,
    float* __restrict__ out,
    int H, long total)
{
    long i = (long)blockIdx.x * blockDim.x + threadIdx.x;
    if (i >= total) return;
    int row = (int)(i / H);
    float scale_x = scale_x_v[row];
    float scale_y = scale_y_v[row];
    float f   = decode_elem(x[i]);
    float xf  = f * scale_x;
    float e   = exp2f(-xf * LOG2E);
    float sig = __frcp_rn(1.0f + e);
    float yq  = fminf(rintf(sig / scale_y), 127.0f);
    float oq  = rintf(xf * (yq * scale_y) / scale_out_v[row]);
    out[i] = fminf(fmaxf(oq, -127.0f), 127.0f);
}

__global__ void tail_pad_kernel(const float* __restrict__ scale_o,
                                float* __restrict__ dst, int S, long extra) {
    long i = (long)blockIdx.x * blockDim.x + threadIdx.x;
    if (i >= extra) return;
    dst[i] = (i < S) ? scale_o[i] : 0.0f;
}

extern "C" void kernel_launch(void* const* d_in, const int* in_sizes, int n_in,
                              void* d_out, int out_size) {
    const void* x         = d_in[0];
    const float* scale_x  = (const float*)d_in[1];
    const float* scale_y  = (const float*)d_in[2];
    const float* scale_o  = (const float*)d_in[3];

    int S = in_sizes[1];            // rows (scale_x element count)
    int H = in_sizes[0] / S;        // cols
    long total = (long)S * H;
    long extra = (long)out_size - total;
    float* out = (float*)d_out;

    if (H == 4096) {
        int write_tail = (extra >= (long)S) ? 1 : 0;
        silu_lut_kernel<<<S, 256>>>(
            (const int4*)x, scale_x, scale_y, scale_o,
            (float4*)out, out + total, write_tail);
        if (extra > (long)S) {
            long pad = extra - S;
            tail_pad_kernel<<<(int)((pad + 255) / 256), 256>>>(
                scale_o + S, out + total + S, 0, pad);
        } else if (extra > 0 && !write_tail) {
            tail_pad_kernel<<<(int)((extra + 255) / 256), 256>>>(
                scale_o, out + total, (int)extra, extra);
        }
    } else {
        long blocks = (total + 255) / 256;
        silu_quant_generic_kernel<<<(unsigned)blocks, 256>>>(
            (const int*)x, scale_x, scale_y, scale_o, out, H, total);
        if (extra > 0) {
            tail_pad_kernel<<<(int)((extra + 255) / 256), 256>>>(
                scale_o, out + total, (int)(extra < S ? extra : S), extra);
        }
    }
}